// round 10
// baseline (speedup 1.0000x reference)
#include <cuda_runtime.h>

// SimpleQNN full analytic collapse:
//   z_j[b] = cos(rx_j) * sin(x[b,j] - ry_j)   (RY·H·RY·RX composition)
//   rz/crz diagonal -> dead; CNOT chain -> parity observables:
//   q[b,w] = prod_{0..w} z (w>=1), q[b,0] = prod_{1..15} z
//   out = q @ W^T + bias
//
// R9 == R8 resubmit (R8 bench was an infra failure, kernel never ran):
// grid=1 x 1024; communication is WARP-LOCAL: one warp owns two batches
// (lanes 0-15 = batch A wires, lanes 16-31 = batch B). The smem z exchange
// needs only __syncwarp() -- no block-wide __syncthreads coupling all 32
// warps to the slowest warp's L2 latency. Warps independent end-to-end.

#define NW 16
#define NOUT 10
#define BATCH 64
#define FULL 0xffffffffu

__global__ void __launch_bounds__(BATCH * NW)
qnn_analytic_kernel(const float* __restrict__ x,     // [64,16]
                    const float* __restrict__ ryp,   // [16]
                    const float* __restrict__ rxp,   // [16]
                    const float* __restrict__ W,     // [10,16]
                    const float* __restrict__ bias,  // [10]
                    float* __restrict__ out)         // [64,10]
{
    __shared__ float zsm[BATCH][NW];   // 4 KB; each warp touches only its 2 rows

    const int tid  = threadIdx.x;      // 0..1023 == b*16 + j
    const int j    = tid & 15;         // wire (stage1) / output col (stage2)
    const int b    = tid >> 4;         // batch

    // ---- stage 1: per-(b,j) Z expectation; x load perfectly coalesced
    zsm[b][j] = __cosf(rxp[j]) * __sinf(x[tid] - ryp[j]);

    // ---- prefetch linear-head operands (overlaps stage1 latency)
    float4 w0, w1, w2, w3;
    float  bv = 0.0f;
    if (j < NOUT) {
        const float4* Wr = (const float4*)(W + j * NW);
        w0 = Wr[0]; w1 = Wr[1]; w2 = Wr[2]; w3 = Wr[3];
        bv = bias[j];
    }

    // warp-local exchange: lanes read only rows their own warp wrote
    __syncwarp(FULL);

    // ---- stage 2: lanes j<10 of each 16-lane group produce out[b][j]
    if (j < NOUT) {
        float* const op = out + b * NOUT + j;

        const float4* zr = (const float4*)zsm[b];    // broadcast within group
        float4 za = zr[0], zb = zr[1], zc = zr[2], zd = zr[3];
        float zv[NW] = { za.x, za.y, za.z, za.w,  zb.x, zb.y, zb.z, zb.w,
                         zc.x, zc.y, zc.z, zc.w,  zd.x, zd.y, zd.z, zd.w };

        // prefix products: q[w] = z0*...*zw  (w >= 1)
        float q[NW];
        float pref = zv[0];
#pragma unroll
        for (int w = 1; w < NW; ++w) { pref *= zv[w]; q[w] = pref; }
        // q[0] = prod_{1..15}: two parallel sub-products, then one mul
        float s1 = zv[1];
#pragma unroll
        for (int w = 2; w <= 8; ++w)  s1 *= zv[w];
        float s2 = zv[9];
#pragma unroll
        for (int w = 10; w < NW; ++w) s2 *= zv[w];
        q[0] = s1 * s2;

        // dot with prefetched W row, 2 independent accumulators
        const float wv[NW] = { w0.x, w0.y, w0.z, w0.w,  w1.x, w1.y, w1.z, w1.w,
                               w2.x, w2.y, w2.z, w2.w,  w3.x, w3.y, w3.z, w3.w };
        float a0 = bv, a1 = 0.0f;
#pragma unroll
        for (int w = 0; w < NW; w += 2) {
            a0 = fmaf(q[w],     wv[w],     a0);
            a1 = fmaf(q[w + 1], wv[w + 1], a1);
        }
        *op = a0 + a1;
    }
}

extern "C" void kernel_launch(void* const* d_in, const int* in_sizes, int n_in,
                              void* d_out, int out_size)
{
    // metadata order: x, ry_params, rx_params, rz_params, crz_params, W, b
    const float* x    = (const float*)d_in[0];
    const float* ryp  = (const float*)d_in[1];
    const float* rxp  = (const float*)d_in[2];
    // d_in[3] (rz) / d_in[4] (crz): diagonal gates, provably no effect on probs
    const float* W    = (const float*)d_in[5];
    const float* bias = (const float*)d_in[6];
    float* out = (float*)d_out;

    qnn_analytic_kernel<<<1, BATCH * NW>>>(x, ryp, rxp, W, bias, out);
}

// round 12
// speedup vs baseline: 1.0385x; 1.0385x over previous
#include <cuda_runtime.h>

// SimpleQNN full analytic collapse:
//   z_j[b] = cos(rx_j) * sin(x[b,j] - ry_j)   (RY·H·RY·RX composition)
//   rz/crz diagonal -> dead; CNOT chain -> parity observables:
//   q[b,w] = prod_{0..w} z (w>=1), q[b,0] = prod_{1..15} z
//   out = q @ W^T + bias
//
// R11 == R10 with the bias-index bug fixed (bias[k & 9] collapsed to
// bias[k&1] since NOUT=10 is not a power of two; now plain bias[k]).
// Layout: 512 threads (16 warps), 2 adjacent wires per thread; one float2
// x-load + 4 MUFU + STS.64; warp-local syncwarp; stage 2 rebuilds the batch
// row via 4x LDS.128 (rows padded to 80 B, 16B-aligned), prefix/suffix
// products, 10 outputs from 8 threads/batch (l<8: k=l; l<2 also k=l+8).

#define NW 16
#define NROW 20            // padded row: 80 B (16B-aligned, conflict-spread)
#define NOUT 10
#define BATCH 64
#define FULL 0xffffffffu

__global__ void __launch_bounds__(512)
qnn_analytic_kernel(const float* __restrict__ x,     // [64,16]
                    const float* __restrict__ ryp,   // [16]
                    const float* __restrict__ rxp,   // [16]
                    const float* __restrict__ W,     // [10,16]
                    const float* __restrict__ bias,  // [10]
                    float* __restrict__ out)         // [64,10]
{
    __shared__ float zsm[BATCH][NROW];   // 5 KB; each warp touches 4 rows

    const int tid = threadIdx.x;         // 0..511
    const int b   = tid >> 3;            // batch (8 threads per batch)
    const int l   = tid & 7;             // sub-lane within batch
    const int jp  = l << 1;              // wires jp, jp+1

    // ---- stage 1: two wires per thread; x load is a coalesced float2
    const float2 xv = *(const float2*)(x + (tid << 1));   // x[b][jp], x[b][jp+1]
    float z0 = __cosf(rxp[jp])     * __sinf(xv.x - ryp[jp]);
    float z1 = __cosf(rxp[jp + 1]) * __sinf(xv.y - ryp[jp + 1]);
    *(float2*)&zsm[b][jp] = make_float2(z0, z1);          // STS.64

    // ---- prefetch linear-head operands (overlap stage-1 latency)
    const int k = l;                       // primary output column, k in [0,8)
    float4 w0, w1, w2, w3;                 // W row k
    float  bv = bias[k];                   // FIXED: direct index (always valid)
    {
        const float4* Wr = (const float4*)(W + k * NW);
        w0 = Wr[0]; w1 = Wr[1]; w2 = Wr[2]; w3 = Wr[3];
    }
    float4 v0, v1, v2, v3;                 // W row k+8 (only lanes l<2)
    float  bv2 = 0.0f;
    if (l < 2) {
        const float4* Wr2 = (const float4*)(W + (k + 8) * NW);
        v0 = Wr2[0]; v1 = Wr2[1]; v2 = Wr2[2]; v3 = Wr2[3];
        bv2 = bias[k + 8];
    }

    // warp-local exchange: a warp wrote exactly the 4 rows it reads
    __syncwarp(FULL);

    // ---- stage 2: rebuild z row (broadcast LDS.128), products, dots
    const float4* zr = (const float4*)zsm[b];
    float4 za = zr[0], zb = zr[1], zc = zr[2], zd = zr[3];
    float zv[NW] = { za.x, za.y, za.z, za.w,  zb.x, zb.y, zb.z, zb.w,
                     zc.x, zc.y, zc.z, zc.w,  zd.x, zd.y, zd.z, zd.w };

    // prefix products q[w] = z0*...*zw (w>=1); q[0] = prod_{1..15}
    float q[NW];
    float pref = zv[0];
#pragma unroll
    for (int w = 1; w < NW; ++w) { pref *= zv[w]; q[w] = pref; }
    float s1 = zv[1];
#pragma unroll
    for (int w = 2; w <= 8; ++w)  s1 *= zv[w];
    float s2 = zv[9];
#pragma unroll
    for (int w = 10; w < NW; ++w) s2 *= zv[w];
    q[0] = s1 * s2;

    // primary output k = l (all 8 sub-lanes)
    {
        const float wv[NW] = { w0.x, w0.y, w0.z, w0.w,  w1.x, w1.y, w1.z, w1.w,
                               w2.x, w2.y, w2.z, w2.w,  w3.x, w3.y, w3.z, w3.w };
        float a0 = bv, a1 = 0.0f;
#pragma unroll
        for (int w = 0; w < NW; w += 2) {
            a0 = fmaf(q[w],     wv[w],     a0);
            a1 = fmaf(q[w + 1], wv[w + 1], a1);
        }
        out[b * NOUT + k] = a0 + a1;
    }
    // secondary output k+8 (sub-lanes 0,1 only)
    if (l < 2) {
        const float vv[NW] = { v0.x, v0.y, v0.z, v0.w,  v1.x, v1.y, v1.z, v1.w,
                               v2.x, v2.y, v2.z, v2.w,  v3.x, v3.y, v3.z, v3.w };
        float a0 = bv2, a1 = 0.0f;
#pragma unroll
        for (int w = 0; w < NW; w += 2) {
            a0 = fmaf(q[w],     vv[w],     a0);
            a1 = fmaf(q[w + 1], vv[w + 1], a1);
        }
        out[b * NOUT + k + 8] = a0 + a1;
    }
}

extern "C" void kernel_launch(void* const* d_in, const int* in_sizes, int n_in,
                              void* d_out, int out_size)
{
    // metadata order: x, ry_params, rx_params, rz_params, crz_params, W, b
    const float* x    = (const float*)d_in[0];
    const float* ryp  = (const float*)d_in[1];
    const float* rxp  = (const float*)d_in[2];
    // d_in[3] (rz) / d_in[4] (crz): diagonal gates, provably no effect on probs
    const float* W    = (const float*)d_in[5];
    const float* bias = (const float*)d_in[6];
    float* out = (float*)d_out;

    qnn_analytic_kernel<<<1, 512>>>(x, ryp, rxp, W, bias, out);
}